// round 5
// baseline (speedup 1.0000x reference)
#include <cuda_runtime.h>

#define BATCH 16
#define NANCH 25200
#define NCLS  80
#define TOPK  2048
#define KW    32   // TOPK/64 words of suppression bits

typedef unsigned long long u64;
typedef unsigned int u32;

// ---------------- scratch (static device globals; no allocation) -------------
__device__ float  g_score[BATCH * NANCH];
__device__ int    g_label[BATCH * NANCH];
__device__ float4 g_top_boxes[BATCH * TOPK];
__device__ float  g_top_scores[BATCH * TOPK];
__device__ int    g_top_labels[BATCH * TOPK];
__device__ u64    g_supp[(size_t)BATCH * TOPK * KW];   // 8 MB suppression bitmatrix
__device__ u64    g_keep[BATCH * KW];

// ---------------- stage 1: obj*cls max + argmax + conf filter ----------------
// Replicates: scores_all = obj[...,None]*probs; max/argmax over classes;
// conf filter (>0.25 else 0). Strict '>' ascending scan == first-occurrence
// argmax of the *rounded products* (matches jnp exactly).
__global__ void __launch_bounds__(256) k_score(const float* __restrict__ obj,
                                               const float* __restrict__ probs) {
    int t = blockIdx.x * 256 + threadIdx.x;
    if (t >= BATCH * NANCH) return;
    float o = obj[t];
    const float4* p = reinterpret_cast<const float4*>(probs) + (size_t)t * (NCLS / 4);
    float best = -1.0f;
    int bl = 0;
#pragma unroll
    for (int i = 0; i < NCLS / 4; i++) {
        float4 v = p[i];
        float s;
        s = __fmul_rn(o, v.x); if (s > best) { best = s; bl = 4 * i + 0; }
        s = __fmul_rn(o, v.y); if (s > best) { best = s; bl = 4 * i + 1; }
        s = __fmul_rn(o, v.z); if (s > best) { best = s; bl = 4 * i + 2; }
        s = __fmul_rn(o, v.w); if (s > best) { best = s; bl = 4 * i + 3; }
    }
    g_score[t] = (best > 0.25f) ? best : 0.0f;
    g_label[t] = bl;
}

// ---------------- stage 2: stable top-2048 per image -------------------------
// Scores above conf lie in (0.25, 1.0]: float bits span [0x3E800001, 0x3F800000],
// a 2^24 code range. Histogram on (bits-0x3E800000)>>13 -> 2048 bins; suffix
// scan picks the threshold bin; compacted candidates (key=(bits<<16)|(65535-idx),
// idx<25200<65536) bitonic-sorted descending -> stable top-K identical to
// jax.lax.top_k (ties: lower index first).
__global__ void __launch_bounds__(1024) k_topk(const float* __restrict__ boxes) {
    __shared__ u32 hist[2048];
    __shared__ u64 buf[4096];
    __shared__ int shT;
    __shared__ u32 shCnt;
    int b = blockIdx.x;
    int tid = threadIdx.x;
    const float* sc = g_score + (size_t)b * NANCH;

    hist[tid] = 0u; hist[tid + 1024] = 0u;
    if (tid == 0) { shT = 0; shCnt = 0u; }
    __syncthreads();

    for (int n = tid; n < NANCH; n += 1024) {
        float s = sc[n];
        if (s > 0.0f) {
            u32 bits = __float_as_uint(s);
            u32 bin = (bits - 0x3E800000u) >> 13;
            if (bin > 2047u) bin = 2047u;
            atomicAdd(&hist[bin], 1u);
        }
    }
    __syncthreads();

    // in-place suffix sums: hist[b] = count of elements in bins >= b
    for (int off = 1; off < 2048; off <<= 1) {
        u32 v0 = (tid + off < 2048) ? hist[tid + off] : 0u;
        u32 v1 = (tid + 1024 + off < 2048) ? hist[tid + 1024 + off] : 0u;
        __syncthreads();
        hist[tid] += v0;
        hist[tid + 1024] += v1;
        __syncthreads();
    }

    // threshold bin T: suffix(T) >= K, suffix(T+1) < K (T=0 if total < K)
    for (int bb = tid; bb < 2048; bb += 1024) {
        u32 sb = hist[bb];
        u32 sb1 = (bb == 2047) ? 0u : hist[bb + 1];
        if (sb >= (u32)TOPK && sb1 < (u32)TOPK) shT = bb;
    }
    __syncthreads();
    u32 T = (u32)shT;

    for (int n = tid; n < NANCH; n += 1024) {
        float s = sc[n];
        if (s > 0.0f) {
            u32 bits = __float_as_uint(s);
            u32 bin = (bits - 0x3E800000u) >> 13;
            if (bin > 2047u) bin = 2047u;
            if (bin >= T) {
                u32 pos = atomicAdd(&shCnt, 1u);
                if (pos < 4096u) buf[pos] = ((u64)bits << 16) | (u64)(u32)(65535 - n);
            }
        }
    }
    __syncthreads();
    u32 M = shCnt; if (M > 4096u) M = 4096u;
    for (u32 i = M + tid; i < 4096u; i += 1024u) buf[i] = 0ull;

    // bitonic sort 4096 u64, descending
    for (u32 kk = 2; kk <= 4096; kk <<= 1) {
        for (u32 j = kk >> 1; j > 0; j >>= 1) {
            __syncthreads();
            for (u32 i = tid; i < 4096; i += 1024) {
                u32 l = i ^ j;
                if (l > i) {
                    u64 a = buf[i], c = buf[l];
                    bool dir = ((i & kk) == 0);   // descending region
                    if ((a < c) == dir) { buf[i] = c; buf[l] = a; }
                }
            }
        }
    }
    __syncthreads();

    for (int k = tid; k < TOPK; k += 1024) {
        u64 key = buf[k];
        u32 bits = (u32)(key >> 16);
        float4 bx = make_float4(0.f, 0.f, 0.f, 0.f);
        float s = 0.0f;
        int lab = 0;
        if (bits != 0u) {
            int idx = 65535 - (int)(key & 0xFFFFull);
            s = __uint_as_float(bits);
            bx = reinterpret_cast<const float4*>(boxes)[(size_t)b * NANCH + idx];
            lab = g_label[(size_t)b * NANCH + idx];
        }
        g_top_boxes[b * TOPK + k] = bx;
        g_top_scores[b * TOPK + k] = s;
        g_top_labels[b * TOPK + k] = lab;
    }
}

// ---------------- stage 3: IoU suppression bit-matrix ------------------------
// supp[i] word w: bit jj set iff box i suppresses box j=64w+jj (j>i, iou>0.45).
// Fast path: sign of inter - 0.45*union; borderline (|d|<=1e-5*union) falls
// back to IEEE division so the predicate is bit-identical to the reference.
__global__ void __launch_bounds__(256) k_iou() {
    __shared__ float4 cb[512];
    __shared__ float  ca[512];
    int b = blockIdx.z;
    int row = blockIdx.x * 32 + threadIdx.x;
    int w = blockIdx.y * 8 + threadIdx.y;
    int colbase = blockIdx.y * 512;
    int t = threadIdx.y * 32 + threadIdx.x;

    for (int i = t; i < 512; i += 256) {
        float4 v = g_top_boxes[b * TOPK + colbase + i];
        cb[i] = v;
        ca[i] = __fmul_rn(__fadd_rn(v.z, -v.x), __fadd_rn(v.w, -v.y));
    }
    __syncthreads();

    float4 rb = g_top_boxes[b * TOPK + row];
    float rarea = __fmul_rn(__fadd_rn(rb.z, -rb.x), __fadd_rn(rb.w, -rb.y));

    u64 bits = 0ull;
    int jbase = w * 64;
    if (jbase + 63 > row) {
        int j0 = threadIdx.y * 64;   // local smem base for this word
#pragma unroll 4
        for (int jj = 0; jj < 64; jj++) {
            int jg = jbase + jj;
            if (jg > row) {
                float4 c = cb[j0 + jj];
                float ax = fmaxf(rb.x, c.x);
                float ay = fmaxf(rb.y, c.y);
                float bx = fminf(rb.z, c.z);
                float by = fminf(rb.w, c.w);
                float ww = fmaxf(__fadd_rn(bx, -ax), 0.0f);
                float hh = fmaxf(__fadd_rn(by, -ay), 0.0f);
                float inter = __fmul_rn(ww, hh);
                float uni = __fadd_rn(__fadd_rn(rarea, ca[j0 + jj]), -inter);
                float d = __fmaf_rn(uni, -0.45f, inter);
                bool sup;
                if (fabsf(d) > 1e-5f * uni) sup = (d > 0.0f);
                else                        sup = (__fdiv_rn(inter, uni) > 0.45f);
                if (sup) bits |= (1ull << jj);
            }
        }
    }
    g_supp[((size_t)b * TOPK + row) * KW + w] = bits;
}

// ---------------- stage 4: sequential greedy NMS -----------------------------
// One warp per image; lane j owns removed-word j (64 bits). Per row: broadcast
// the row's flag word via shfl, branchless mask, OR the row's suppression word.
// removed is pre-seeded with ~keep0 so dead rows never suppress.
__global__ void __launch_bounds__(32) k_nms() {
    int b = blockIdx.x;
    int lane = threadIdx.x;
    const float* ts = g_top_scores + b * TOPK;

    u64 rem = 0ull;
#pragma unroll 8
    for (int k = 0; k < 64; k++) {
        if (!(ts[lane * 64 + k] > 0.0f)) rem |= (1ull << k);
    }

    const u64* supp = g_supp + (size_t)b * TOPK * KW;
#pragma unroll 4
    for (int i = 0; i < TOPK; i++) {
        u64 wv = __shfl_sync(0xffffffffu, rem, i >> 6);
        u64 alivem = ((wv >> (i & 63)) & 1ull) - 1ull;  // all-ones if alive
        rem |= supp[(size_t)i * KW + lane] & alivem;
    }
    g_keep[b * KW + lane] = ~rem;   // keep0 & !suppressed
}

// ---------------- stage 5: finalize outputs ----------------------------------
// d_out layout (flattened tuple, float32): boxes[16,2048,4] | scores[16,2048]
// | labels[16,2048] (labels value-cast to float).
__global__ void __launch_bounds__(256) k_final(float* __restrict__ out) {
    int t = blockIdx.x * 256 + threadIdx.x;
    if (t >= BATCH * TOPK) return;
    int b = t / TOPK, k = t % TOPK;
    u64 kw = g_keep[b * KW + (k >> 6)];
    bool keep = ((kw >> (k & 63)) & 1ull) != 0ull;
    float4 bx = g_top_boxes[t];
    float s = g_top_scores[t];
    int lab = g_top_labels[t];
    reinterpret_cast<float4*>(out)[t] = keep ? bx : make_float4(0.f, 0.f, 0.f, 0.f);
    out[BATCH * TOPK * 4 + t] = keep ? s : 0.0f;
    out[BATCH * TOPK * 5 + t] = keep ? (float)lab : 0.0f;
}

// ---------------- launch ------------------------------------------------------
extern "C" void kernel_launch(void* const* d_in, const int* in_sizes, int n_in,
                              void* d_out, int out_size) {
    const float* boxes = (const float*)d_in[0];
    const float* obj   = (const float*)d_in[1];
    const float* probs = (const float*)d_in[2];

    k_score<<<(BATCH * NANCH + 255) / 256, 256>>>(obj, probs);
    k_topk<<<BATCH, 1024>>>(boxes);
    k_iou<<<dim3(TOPK / 32, KW / 8, BATCH), dim3(32, 8)>>>();
    k_nms<<<BATCH, 32>>>();
    k_final<<<(BATCH * TOPK + 255) / 256, 256>>>((float*)d_out);
}

// round 8
// speedup vs baseline: 1.8156x; 1.8156x over previous
#include <cuda_runtime.h>

#define BATCH 16
#define NANCH 25200
#define NCLS  80
#define TOPK  2048
#define KW    32     // TOPK/64 words of suppression bits
#define TSTRIDE 33   // padded tile row stride (words) -> 2-way LDS conflicts max

typedef unsigned long long u64;
typedef unsigned int u32;

// ---------------- scratch (static device globals; no allocation) -------------
__device__ float  g_score[BATCH * NANCH];
__device__ int    g_label[BATCH * NANCH];
__device__ float4 g_top_boxes[BATCH * TOPK];
__device__ float  g_top_scores[BATCH * TOPK];
__device__ int    g_top_labels[BATCH * TOPK];
__device__ u64    g_supp[(size_t)BATCH * TOPK * KW];   // 8 MB suppression bitmatrix
__device__ u64    g_keep[BATCH * KW];

// ---------------- cp.async helpers ------------------------------------------
__device__ __forceinline__ void cp_async8(void* dst_smem, const void* src) {
    u32 d = (u32)__cvta_generic_to_shared(dst_smem);
    asm volatile("cp.async.ca.shared.global [%0], [%1], 8;\n" :: "r"(d), "l"(src));
}
__device__ __forceinline__ void cp_commit() {
    asm volatile("cp.async.commit_group;\n");
}
template <int N>
__device__ __forceinline__ void cp_wait() {
    asm volatile("cp.async.wait_group %0;\n" :: "n"(N));
}

// ---------------- stage 1: obj*cls max + argmax + conf filter ----------------
// Replicates: scores_all = obj[...,None]*probs; max/argmax over classes;
// conf filter (>0.25 else 0). Strict '>' ascending scan == first-occurrence
// argmax of the *rounded products* (matches jnp exactly).
__global__ void __launch_bounds__(256) k_score(const float* __restrict__ obj,
                                               const float* __restrict__ probs) {
    int t = blockIdx.x * 256 + threadIdx.x;
    if (t >= BATCH * NANCH) return;
    float o = obj[t];
    const float4* p = reinterpret_cast<const float4*>(probs) + (size_t)t * (NCLS / 4);
    float best = -1.0f;
    int bl = 0;
#pragma unroll
    for (int i = 0; i < NCLS / 4; i++) {
        float4 v = p[i];
        float s;
        s = __fmul_rn(o, v.x); if (s > best) { best = s; bl = 4 * i + 0; }
        s = __fmul_rn(o, v.y); if (s > best) { best = s; bl = 4 * i + 1; }
        s = __fmul_rn(o, v.z); if (s > best) { best = s; bl = 4 * i + 2; }
        s = __fmul_rn(o, v.w); if (s > best) { best = s; bl = 4 * i + 3; }
    }
    g_score[t] = (best > 0.25f) ? best : 0.0f;
    g_label[t] = bl;
}

// ---------------- stage 2: stable top-2048 per image -------------------------
// Histogram on score bits -> threshold bin -> compact -> 4096-wide bitonic
// sort on key=(bits<<16)|(65535-idx): stable top-K identical to jax.lax.top_k.
__global__ void __launch_bounds__(1024) k_topk(const float* __restrict__ boxes) {
    __shared__ u32 hist[2048];
    __shared__ u64 buf[4096];
    __shared__ int shT;
    __shared__ u32 shCnt;
    int b = blockIdx.x;
    int tid = threadIdx.x;
    const float* sc = g_score + (size_t)b * NANCH;

    hist[tid] = 0u; hist[tid + 1024] = 0u;
    if (tid == 0) { shT = 0; shCnt = 0u; }
    __syncthreads();

    for (int n = tid; n < NANCH; n += 1024) {
        float s = sc[n];
        if (s > 0.0f) {
            u32 bits = __float_as_uint(s);
            u32 bin = (bits - 0x3E800000u) >> 13;
            if (bin > 2047u) bin = 2047u;
            atomicAdd(&hist[bin], 1u);
        }
    }
    __syncthreads();

    for (int off = 1; off < 2048; off <<= 1) {
        u32 v0 = (tid + off < 2048) ? hist[tid + off] : 0u;
        u32 v1 = (tid + 1024 + off < 2048) ? hist[tid + 1024 + off] : 0u;
        __syncthreads();
        hist[tid] += v0;
        hist[tid + 1024] += v1;
        __syncthreads();
    }

    for (int bb = tid; bb < 2048; bb += 1024) {
        u32 sb = hist[bb];
        u32 sb1 = (bb == 2047) ? 0u : hist[bb + 1];
        if (sb >= (u32)TOPK && sb1 < (u32)TOPK) shT = bb;
    }
    __syncthreads();
    u32 T = (u32)shT;

    for (int n = tid; n < NANCH; n += 1024) {
        float s = sc[n];
        if (s > 0.0f) {
            u32 bits = __float_as_uint(s);
            u32 bin = (bits - 0x3E800000u) >> 13;
            if (bin > 2047u) bin = 2047u;
            if (bin >= T) {
                u32 pos = atomicAdd(&shCnt, 1u);
                if (pos < 4096u) buf[pos] = ((u64)bits << 16) | (u64)(u32)(65535 - n);
            }
        }
    }
    __syncthreads();
    u32 M = shCnt; if (M > 4096u) M = 4096u;
    for (u32 i = M + tid; i < 4096u; i += 1024u) buf[i] = 0ull;

    for (u32 kk = 2; kk <= 4096; kk <<= 1) {
        for (u32 j = kk >> 1; j > 0; j >>= 1) {
            __syncthreads();
            for (u32 i = tid; i < 4096; i += 1024) {
                u32 l = i ^ j;
                if (l > i) {
                    u64 a = buf[i], c = buf[l];
                    bool dir = ((i & kk) == 0);
                    if ((a < c) == dir) { buf[i] = c; buf[l] = a; }
                }
            }
        }
    }
    __syncthreads();

    for (int k = tid; k < TOPK; k += 1024) {
        u64 key = buf[k];
        u32 bits = (u32)(key >> 16);
        float4 bx = make_float4(0.f, 0.f, 0.f, 0.f);
        float s = 0.0f;
        int lab = 0;
        if (bits != 0u) {
            int idx = 65535 - (int)(key & 0xFFFFull);
            s = __uint_as_float(bits);
            bx = reinterpret_cast<const float4*>(boxes)[(size_t)b * NANCH + idx];
            lab = g_label[(size_t)b * NANCH + idx];
        }
        g_top_boxes[b * TOPK + k] = bx;
        g_top_scores[b * TOPK + k] = s;
        g_top_labels[b * TOPK + k] = lab;
    }
}

// ---------------- stage 3: IoU suppression bit-matrix ------------------------
// supp[i] word w: bit jj set iff box i suppresses box j=64w+jj (j>i, iou>0.45).
// Borderline pairs fall back to IEEE division: bit-identical to reference.
__global__ void __launch_bounds__(256) k_iou() {
    __shared__ float4 cb[512];
    __shared__ float  ca[512];
    int b = blockIdx.z;
    int row = blockIdx.x * 32 + threadIdx.x;
    int w = blockIdx.y * 8 + threadIdx.y;
    int colbase = blockIdx.y * 512;
    int t = threadIdx.y * 32 + threadIdx.x;

    for (int i = t; i < 512; i += 256) {
        float4 v = g_top_boxes[b * TOPK + colbase + i];
        cb[i] = v;
        ca[i] = __fmul_rn(__fadd_rn(v.z, -v.x), __fadd_rn(v.w, -v.y));
    }
    __syncthreads();

    float4 rb = g_top_boxes[b * TOPK + row];
    float rarea = __fmul_rn(__fadd_rn(rb.z, -rb.x), __fadd_rn(rb.w, -rb.y));

    u64 bits = 0ull;
    int jbase = w * 64;
    if (jbase + 63 > row) {
        int j0 = threadIdx.y * 64;
#pragma unroll 4
        for (int jj = 0; jj < 64; jj++) {
            int jg = jbase + jj;
            if (jg > row) {
                float4 c = cb[j0 + jj];
                float ax = fmaxf(rb.x, c.x);
                float ay = fmaxf(rb.y, c.y);
                float bx = fminf(rb.z, c.z);
                float by = fminf(rb.w, c.w);
                float ww = fmaxf(__fadd_rn(bx, -ax), 0.0f);
                float hh = fmaxf(__fadd_rn(by, -ay), 0.0f);
                float inter = __fmul_rn(ww, hh);
                float uni = __fadd_rn(__fadd_rn(rarea, ca[j0 + jj]), -inter);
                float d = __fmaf_rn(uni, -0.45f, inter);
                bool sup;
                if (fabsf(d) > 1e-5f * uni) sup = (d > 0.0f);
                else                        sup = (__fdiv_rn(inter, uni) > 0.45f);
                if (sup) bits |= (1ull << jj);
            }
        }
    }
    g_supp[((size_t)b * TOPK + row) * KW + w] = bits;
}

// ---------------- stage 4: block-parallel greedy NMS -------------------------
// 1 CTA (1024 thr) per image. 32 blocks of 64 rows, ascending:
//   Phase A (thread 0): serial 64-step intra-block resolve on the smem tile's
//                       diagonal word (same accept order as the reference scan).
//   Phase B (warps > blk): accepted rows' suppression words OR-reduced
//                          (redux.sync) into rem[] for all later blocks.
// Tiles (64 rows x 32 words) are double-buffered via cp.async, issued one
// block ahead, so L2 latency never sits on the serial chain.
__global__ void __launch_bounds__(1024) k_nms() {
    __shared__ u64 tile[2][64 * TSTRIDE];
    __shared__ u64 rem[KW];
    __shared__ u64 accsh;

    int b = blockIdx.x;
    int tid = threadIdx.x;
    int w = tid >> 5;       // warp id == word id
    int lane = tid & 31;
    const float* ts = g_top_scores + b * TOPK;
    const u64* supp = g_supp + (size_t)b * TOPK * KW;

    // seed rem with conf-dead bits (warp w -> word w)
    {
        bool a0 = ts[w * 64 + lane] > 0.0f;
        bool a1 = ts[w * 64 + 32 + lane] > 0.0f;
        u32 lo = __ballot_sync(0xffffffffu, a0);
        u32 hi = __ballot_sync(0xffffffffu, a1);
        if (lane == 0) rem[w] = ~(((u64)hi << 32) | (u64)lo);
    }

    // each thread copies words 2*tid, 2*tid+1 of the 2048-word tile
    int trow = tid >> 4;              // row within block (0..63)
    int tword = (tid * 2) & 31;       // even word within row
    // prologue: stage tile for block 0
    cp_async8(&tile[0][trow * TSTRIDE + tword],     supp + tid * 2);
    cp_async8(&tile[0][trow * TSTRIDE + tword + 1], supp + tid * 2 + 1);
    cp_commit();

    for (int blk = 0; blk < KW; blk++) {
        int cur = blk & 1, nxt = cur ^ 1;
        if (blk + 1 < KW) {
            const u64* src = supp + (size_t)(blk + 1) * 2048 + tid * 2;
            cp_async8(&tile[nxt][trow * TSTRIDE + tword],     src);
            cp_async8(&tile[nxt][trow * TSTRIDE + tword + 1], src + 1);
            cp_commit();
            cp_wait<1>();   // current block's tile complete
        } else {
            cp_wait<0>();
        }
        __syncthreads();    // tile[cur] + rem[blk] visible to all

        if (tid == 0) {
            const u64* tl = tile[cur];
            u64 removed = rem[blk];
#pragma unroll 8
            for (int k = 0; k < 64; k++) {
                u64 m = tl[k * TSTRIDE + blk];
                if (!((removed >> k) & 1ull)) removed |= m;
            }
            rem[blk] = removed;
            accsh = ~removed;
        }
        __syncthreads();

        if (w > blk) {
            u64 acc = accsh;
            const u64* tl = tile[cur];
            u64 m0 = tl[lane * TSTRIDE + w];
            u64 m1 = tl[(lane + 32) * TSTRIDE + w];
            u64 v = 0ull;
            if ((acc >> lane) & 1ull)        v  = m0;
            if ((acc >> (lane + 32)) & 1ull) v |= m1;
            u32 lo = __reduce_or_sync(0xffffffffu, (u32)v);
            u32 hi = __reduce_or_sync(0xffffffffu, (u32)(v >> 32));
            if (lane == 0) rem[w] |= ((u64)hi << 32) | (u64)lo;
        }
        __syncthreads();
    }

    if (tid < KW) g_keep[b * KW + tid] = ~rem[tid];
}

// ---------------- stage 5: finalize outputs ----------------------------------
__global__ void __launch_bounds__(256) k_final(float* __restrict__ out) {
    int t = blockIdx.x * 256 + threadIdx.x;
    if (t >= BATCH * TOPK) return;
    int b = t / TOPK, k = t % TOPK;
    u64 kw = g_keep[b * KW + (k >> 6)];
    bool keep = ((kw >> (k & 63)) & 1ull) != 0ull;
    float4 bx = g_top_boxes[t];
    float s = g_top_scores[t];
    int lab = g_top_labels[t];
    reinterpret_cast<float4*>(out)[t] = keep ? bx : make_float4(0.f, 0.f, 0.f, 0.f);
    out[BATCH * TOPK * 4 + t] = keep ? s : 0.0f;
    out[BATCH * TOPK * 5 + t] = keep ? (float)lab : 0.0f;
}

// ---------------- launch ------------------------------------------------------
extern "C" void kernel_launch(void* const* d_in, const int* in_sizes, int n_in,
                              void* d_out, int out_size) {
    const float* boxes = (const float*)d_in[0];
    const float* obj   = (const float*)d_in[1];
    const float* probs = (const float*)d_in[2];

    k_score<<<(BATCH * NANCH + 255) / 256, 256>>>(obj, probs);
    k_topk<<<BATCH, 1024>>>(boxes);
    k_iou<<<dim3(TOPK / 32, KW / 8, BATCH), dim3(32, 8)>>>();
    k_nms<<<BATCH, 1024>>>();
    k_final<<<(BATCH * TOPK + 255) / 256, 256>>>((float*)d_out);
}